// round 15
// baseline (speedup 1.0000x reference)
#include <cuda_runtime.h>
#include <math.h>

typedef unsigned long long ull;

#define Bsz 32
#define Ssz 128
#define Tsz 128
#define Hsz 1024
#define G3H 3072
#define Esz 512
#define Vsz 32000
#define NBLK_ENC 444
#define NBLK_DEC 592
#define NBUCKET 37

// ---------------- static scratch ----------------
__device__ float g_gi[(size_t)Ssz * Bsz * G3H];
__device__ float g_ys0[(size_t)Ssz * Bsz * Hsz];
__device__ float g_px[(size_t)16 * Bsz * G3H];
__device__ float g_ph[(size_t)16 * Bsz * G3H];    // L0 h-partials
__device__ float g_ph1[(size_t)16 * Bsz * G3H];   // L1 h-partials
__device__ float g_h1[Bsz * Hsz];
__device__ float g_h2[Bsz * Hsz];
__device__ int g_tok[Bsz];
__device__ ull g_amax[Bsz];
__device__ unsigned g_bar_c1[NBUCKET * 32];
__device__ unsigned g_bar_c2;
__device__ unsigned g_bar_gen;

// ---------------- helpers ----------------
__device__ __forceinline__ ull ffma2(ull a, ull b, ull c) {
    ull d;
    asm("fma.rn.f32x2 %0, %1, %2, %3;" : "=l"(d) : "l"(a), "l"(b), "l"(c));
    return d;
}
__device__ __forceinline__ float2 up2(ull v) {
    float2 f;
    asm("mov.b64 {%0, %1}, %2;" : "=f"(f.x), "=f"(f.y) : "l"(v));
    return f;
}
__device__ __forceinline__ ull packkey(float v, int c) {
    unsigned b = __float_as_uint(v);
    b = (b & 0x80000000u) ? ~b : (b | 0x80000000u);
    return ((ull)b << 32) | (ull)(0xFFFFFFFFu - (unsigned)c);
}
__device__ __forceinline__ void cp16(void* dst, const void* src) {
    unsigned s = (unsigned)__cvta_generic_to_shared(dst);
    asm volatile("cp.async.cg.shared.global [%0], [%1], 16;" :: "r"(s), "l"(src));
}

// grid barrier: 2-level buckets, self-resetting counters, fence-complete.
__device__ __forceinline__ void gbar() {
    __syncthreads();
    __threadfence();
    if (threadIdx.x == 0) {
        unsigned gen;
        asm volatile("ld.acquire.gpu.u32 %0, [%1];"
                     : "=r"(gen) : "l"(&g_bar_gen) : "memory");
        unsigned bsz = gridDim.x / NBUCKET;
        unsigned b = blockIdx.x % NBUCKET;
        bool master = false;
        if (atomicAdd(&g_bar_c1[b * 32], 1u) == bsz - 1u) {
            atomicExch(&g_bar_c1[b * 32], 0u);
            __threadfence();
            if (atomicAdd(&g_bar_c2, 1u) == NBUCKET - 1u) {
                atomicExch(&g_bar_c2, 0u);
                master = true;
            }
        }
        if (master) {
            __threadfence();
            asm volatile("st.release.gpu.u32 [%0], %1;"
                         :: "l"(&g_bar_gen), "r"(gen + 1u) : "memory");
        } else {
            unsigned cur;
            while (true) {
                asm volatile("ld.acquire.gpu.u32 %0, [%1];"
                             : "=r"(cur) : "l"(&g_bar_gen) : "memory");
                if (cur != gen) break;
                __nanosleep(32);
            }
        }
    }
    __syncthreads();
    __threadfence();
}

// ---------------- frozen inner compute: 64-k chunk, K-parity FFMA2 ----------------
// NJ = output columns per thread (width = 16*NJ). K-chain identical regardless of NJ.
template <int NJ>
__device__ __forceinline__ void computeNJ(const float (*As)[68], const float (*Ws)[68],
                                          ull acc[4][NJ], int bg, int cg) {
#pragma unroll 4
    for (int g = 0; g < 16; g++) {
        const int k0 = g * 4;
        ulonglong2 A0 = *(const ulonglong2*)&As[bg][k0];
        ulonglong2 A1 = *(const ulonglong2*)&As[bg + 8][k0];
        ulonglong2 A2 = *(const ulonglong2*)&As[bg + 16][k0];
        ulonglong2 A3 = *(const ulonglong2*)&As[bg + 24][k0];
#pragma unroll
        for (int j = 0; j < NJ; j++) {
            ulonglong2 W01 = *(const ulonglong2*)&Ws[cg + 16 * j][k0];
            acc[0][j] = ffma2(A0.x, W01.x, acc[0][j]);
            acc[1][j] = ffma2(A1.x, W01.x, acc[1][j]);
            acc[2][j] = ffma2(A2.x, W01.x, acc[2][j]);
            acc[3][j] = ffma2(A3.x, W01.x, acc[3][j]);
            acc[0][j] = ffma2(A0.y, W01.y, acc[0][j]);
            acc[1][j] = ffma2(A1.y, W01.y, acc[1][j]);
            acc[2][j] = ffma2(A2.y, W01.y, acc[2][j]);
            acc[3][j] = ffma2(A3.y, W01.y, acc[3][j]);
        }
    }
}

// ---------------- synchronous GEMM task (k_big / k_enc path; 128-col) ----------------
__device__ __noinline__ void gemm_task(
    const float* __restrict__ A, const int* __restrict__ toks, int lda,
    const float* __restrict__ W, int ldw,
    int kbase, int nchunk, int cbase,
    float* __restrict__ outp, int out_ld, const float* __restrict__ bias,
    float (*As)[68], float (*Ws)[68])
{
    const int tid = threadIdx.x;
    const int bg = tid >> 4, cg = tid & 15;
    ull acc[4][8];
#pragma unroll
    for (int i = 0; i < 4; i++)
#pragma unroll
        for (int j = 0; j < 8; j++) acc[i][j] = 0ull;

    for (int ch = 0; ch < nchunk; ch++) {
        const int kb = kbase + ch * 64;
        __syncthreads();
#pragma unroll
        for (int r = 0; r < 4; r++) {
            int f4 = tid + r * 128, row = f4 >> 4, kq = f4 & 15;
            const float* src = toks ? (A + (size_t)toks[row] * lda)
                                    : (A + (size_t)row * lda);
            float4 v = *(const float4*)(src + kb + kq * 4);
            *(float4*)&As[row][kq * 4] = v;
        }
#pragma unroll 4
        for (int r = 0; r < 16; r++) {
            int f4 = tid + r * 128, c = f4 >> 4, kq = f4 & 15;
            float4 v = *(const float4*)(W + (size_t)(cbase + c) * ldw + kb + kq * 4);
            *(float4*)&Ws[c][kq * 4] = v;
        }
        __syncthreads();
        computeNJ<8>(As, Ws, acc, bg, cg);
    }
#pragma unroll
    for (int i = 0; i < 4; i++) {
        float* o = outp + (size_t)(bg + 8 * i) * out_ld + cbase;
#pragma unroll
        for (int j = 0; j < 8; j++) {
            float2 p = up2(acc[i][j]);
            float v = p.x + p.y;
            int c = cg + 16 * j;
            if (bias) v += bias[cbase + c];
            o[c] = v;
        }
    }
}

// ---------------- decoder task descriptors (64-col tiles) ----------------
struct TD { const float* A; const int* toks; const float* W; float* outp;
            int ld, kbase, cbase; };

struct DecCtx {
    const float *demb, *dW0, *dU0, *dW1, *dU1;
    const int* stok;
};

// phase 0 list: [0,384)    gi   (emb@dW0, 8 slices x 48 ct)  -> g_px
//               [384,1152) ghL0 (h1@dU0, 16 slices x 48 ct)  -> g_ph
//               [1152,1920) ghL1 (h2@dU1, 16 slices x 48 ct) -> g_ph1
// phase 1 list: [0,768)    gi2  (h1@dW1, 16 slices x 48 ct)  -> g_px
__device__ __forceinline__ TD dec_task(int phase, int t, const DecCtx& c) {
    TD d;
    if (phase == 0) {
        if (t < 384) {
            int ct = t % 48, s = t / 48;
            d = {c.demb, c.stok, c.dW0, g_px + (size_t)s * Bsz * G3H,
                 Esz, s * 64, ct * 64};
        } else if (t < 1152) {
            int t2 = t - 384, ct = t2 % 48, s = t2 / 48;
            d = {g_h1, nullptr, c.dU0, g_ph + (size_t)s * Bsz * G3H,
                 Hsz, s * 64, ct * 64};
        } else {
            int t2 = t - 1152, ct = t2 % 48, s = t2 / 48;
            d = {g_h2, nullptr, c.dU1, g_ph1 + (size_t)s * Bsz * G3H,
                 Hsz, s * 64, ct * 64};
        }
    } else {
        int ct = t % 48, s = t / 48;
        d = {g_h1, nullptr, c.dW1, g_px + (size_t)s * Bsz * G3H,
             Hsz, s * 64, ct * 64};
    }
    return d;
}

// async 64-col tile load: A 32x64, W 64x64
__device__ __forceinline__ void issue_tile64(const float* A, const int* toks, int ld,
                                             const float* W, int kb, int cbase,
                                             float (*As)[68], float (*Ws)[68], int tid) {
#pragma unroll
    for (int r = 0; r < 4; r++) {
        int f4 = tid + r * 128, row = f4 >> 4, kq = f4 & 15;
        const float* src = toks ? (A + (size_t)toks[row] * ld)
                                : (A + (size_t)row * ld);
        cp16(&As[row][kq * 4], src + kb + kq * 4);
    }
#pragma unroll
    for (int r = 0; r < 8; r++) {
        int f4 = tid + r * 128, c = f4 >> 4, kq = f4 & 15;
        cp16(&Ws[c][kq * 4], W + (size_t)(cbase + c) * ld + kb + kq * 4);
    }
    asm volatile("cp.async.commit_group;" ::: "memory");
}

// pipelined 1-chunk task executor over a strided task list
__device__ __noinline__ void run_tasks(int phase, int i0, int ntask, int stride,
                                       const DecCtx& c,
                                       float (*AsB)[32][68], float (*WsB)[64][68]) {
    const int tid = threadIdx.x;
    const int bg = tid >> 4, cg = tid & 15;
    int i = i0;
    if (i >= ntask) return;
    TD cur = dec_task(phase, i, c);
    int b = 0;
    issue_tile64(cur.A, cur.toks, cur.ld, cur.W, cur.kbase, cur.cbase,
                 AsB[0], WsB[0], tid);
    while (true) {
        int ni = i + stride;
        bool have = (ni < ntask);
        TD nxt;
        if (have) {
            nxt = dec_task(phase, ni, c);
            issue_tile64(nxt.A, nxt.toks, nxt.ld, nxt.W, nxt.kbase, nxt.cbase,
                         AsB[b ^ 1], WsB[b ^ 1], tid);
            asm volatile("cp.async.wait_group 1;" ::: "memory");
        } else {
            asm volatile("cp.async.wait_group 0;" ::: "memory");
        }
        __syncthreads();
        ull acc[4][4];
#pragma unroll
        for (int x = 0; x < 4; x++)
#pragma unroll
            for (int y = 0; y < 4; y++) acc[x][y] = 0ull;
        computeNJ<4>(AsB[b], WsB[b], acc, bg, cg);
#pragma unroll
        for (int x = 0; x < 4; x++) {
            float* o = cur.outp + (size_t)(bg + 8 * x) * G3H + cur.cbase;
#pragma unroll
            for (int y = 0; y < 4; y++) {
                float2 p = up2(acc[x][y]);
                o[cg + 16 * y] = p.x + p.y;
            }
        }
        __syncthreads();
        if (!have) break;
        i = ni; cur = nxt; b ^= 1;
    }
}

// fused FC (64-col tile): bit-exact chain — fcb-first, 8 slices ascending,
// fold acc(.x+.y) into rsum every 2 chunks.
__device__ __noinline__ void run_fc(const float* __restrict__ fcW,
                                    const float* __restrict__ fcb,
                                    float* __restrict__ out, int step,
                                    float (*AsB)[32][68], float (*WsB)[64][68],
                                    ull* sk) {
    const int tid = threadIdx.x, bid = blockIdx.x;
    const int bg = tid >> 4, cg = tid & 15;
    const int cbase = bid * 64;
    if (tid < 32) sk[tid] = 0ull;
    float rsum[4][4];
#pragma unroll
    for (int x = 0; x < 4; x++)
#pragma unroll
        for (int y = 0; y < 4; y++) rsum[x][y] = fcb[cbase + cg + 16 * y];

    issue_tile64(g_h2, nullptr, Hsz, fcW, 0, cbase, AsB[0], WsB[0], tid);
    int b = 0;
    ull acc[4][4];
#pragma unroll
    for (int x = 0; x < 4; x++)
#pragma unroll
        for (int y = 0; y < 4; y++) acc[x][y] = 0ull;
    for (int u = 0; u < 16; u++) {
        if (u + 1 < 16) {
            issue_tile64(g_h2, nullptr, Hsz, fcW, (u + 1) * 64, cbase,
                         AsB[b ^ 1], WsB[b ^ 1], tid);
            asm volatile("cp.async.wait_group 1;" ::: "memory");
        } else {
            asm volatile("cp.async.wait_group 0;" ::: "memory");
        }
        __syncthreads();
        computeNJ<4>(AsB[b], WsB[b], acc, bg, cg);
        if (u & 1) {
#pragma unroll
            for (int x = 0; x < 4; x++)
#pragma unroll
                for (int y = 0; y < 4; y++) {
                    float2 p = up2(acc[x][y]);
                    rsum[x][y] += p.x + p.y;
                    acc[x][y] = 0ull;
                }
        }
        __syncthreads();
        b ^= 1;
    }
#pragma unroll
    for (int x = 0; x < 4; x++) {
        int row = bg + 8 * x;
        float* o = out + (size_t)row * ((size_t)Tsz * Vsz)
                 + (size_t)(step + 1) * Vsz + cbase;
        float bv = -3.4e38f; int bc = 0;
#pragma unroll
        for (int y = 0; y < 4; y++) {
            int c = cg + 16 * y;
            o[c] = rsum[x][y];
            if (rsum[x][y] > bv) { bv = rsum[x][y]; bc = cbase + c; }
        }
        atomicMax(&sk[row], packkey(bv, bc));
    }
    __syncthreads();
    if (tid < 32) atomicMax(&g_amax[tid], sk[tid]);
}

// ---------------- GRU gates + state update (frozen sum order) ----------------
__device__ __forceinline__ void gru_gates(const float* gi_pre, int nx,
                                          const float* bih, int nh,
                                          const float* phb, const float* bhh,
                                          float* h, float* ys, int nblk) {
    for (int idx = blockIdx.x * 128 + threadIdx.x; idx < Bsz * Hsz; idx += nblk * 128) {
        int b = idx >> 10, j = idx & 1023;
        float ir, iz, in_;
        if (gi_pre) {
            const float* g = gi_pre + (size_t)b * G3H;
            ir = g[j]; iz = g[Hsz + j]; in_ = g[2 * Hsz + j];
        } else {
            ir = bih[j]; iz = bih[Hsz + j]; in_ = bih[2 * Hsz + j];
            for (int s = 0; s < nx; s++) {
                const float* p = g_px + (size_t)s * Bsz * G3H + (size_t)b * G3H;
                ir += p[j]; iz += p[Hsz + j]; in_ += p[2 * Hsz + j];
            }
        }
        float hr = bhh[j], hz = bhh[Hsz + j], hn = bhh[2 * Hsz + j];
        for (int s = 0; s < nh; s++) {
            const float* p = phb + (size_t)s * Bsz * G3H + (size_t)b * G3H;
            hr += p[j]; hz += p[Hsz + j]; hn += p[2 * Hsz + j];
        }
        float r = 1.f / (1.f + expf(-(ir + hr)));
        float z = 1.f / (1.f + expf(-(iz + hz)));
        float n = tanhf(in_ + r * hn);
        float hv = h[idx];
        float hnew = (1.f - z) * n + z * hv;
        h[idx] = hnew;
        if (ys) ys[idx] = hnew;
    }
}

// ---------------- small kernels ----------------
__global__ void k_init(const int* __restrict__ trg) {
    int i = blockIdx.x * blockDim.x + threadIdx.x;
    if (i < Bsz * Hsz) { g_h1[i] = 0.f; g_h2[i] = 0.f; }
    if (i < Bsz) { g_tok[i] = trg[i * Tsz]; g_amax[i] = 0ull; }
}

__global__ void k_zero0(float* __restrict__ out) {
    int i = blockIdx.x * blockDim.x + threadIdx.x;
    if (i < Bsz * Vsz) {
        int b = i / Vsz, v = i - b * Vsz;
        out[(size_t)b * ((size_t)Tsz * Vsz) + v] = 0.f;
    }
}

// bulk input-gate GEMM
__global__ void __launch_bounds__(128, 3) k_big(
    const float* __restrict__ emb, const int* __restrict__ src,
    const float* __restrict__ W, const float* __restrict__ bias,
    int K, int gather)
{
    __shared__ float As[32][68];
    __shared__ float Ws[128][68];
    __shared__ int s_tok[32];
    int tid = threadIdx.x, tblk = blockIdx.y, cbase = blockIdx.x * 128;
    const float* A; int lda; const int* tp = nullptr;
    if (gather) {
        if (tid < 32) s_tok[tid] = src[tid * Ssz + tblk];
        __syncthreads();
        tp = s_tok; A = emb; lda = Esz;
    } else {
        A = g_ys0 + (size_t)tblk * Bsz * Hsz; lda = Hsz;
    }
    gemm_task(A, tp, lda, W, K, 0, K / 64, cbase,
              g_gi + (size_t)tblk * Bsz * G3H, G3H, bias, As, Ws);
}

// persistent encoder layer: W tile pinned in smem across all 128 steps.
__global__ void __launch_bounds__(128, 3) k_enc(
    const float* __restrict__ U, const float* __restrict__ bhh, int layer)
{
    __shared__ float As[32][68];
    __shared__ float Ws[128][68];
    const int tid = threadIdx.x, bid = blockIdx.x;
    const int bg = tid >> 4, cg = tid & 15;
    const bool active = bid < 384;
    const int ct = bid % 24, s = bid / 24;
    const int cbase = ct * 128, kb = s * 64;
    float* h = layer ? g_h2 : g_h1;
    if (active) {
#pragma unroll 4
        for (int r = 0; r < 16; r++) {
            int f4 = tid + r * 128, c = f4 >> 4, kq = f4 & 15;
            float4 v = *(const float4*)(U + (size_t)(cbase + c) * Hsz + kb + kq * 4);
            *(float4*)&Ws[c][kq * 4] = v;
        }
    }
    for (int t = 0; t < Ssz; t++) {
        if (active) {
            __syncthreads();
#pragma unroll
            for (int r = 0; r < 4; r++) {
                int f4 = tid + r * 128, row = f4 >> 4, kq = f4 & 15;
                float4 v = *(const float4*)(h + (size_t)row * Hsz + kb + kq * 4);
                *(float4*)&As[row][kq * 4] = v;
            }
            __syncthreads();
            ull acc[4][8];
#pragma unroll
            for (int i = 0; i < 4; i++)
#pragma unroll
                for (int j = 0; j < 8; j++) acc[i][j] = 0ull;
            computeNJ<8>(As, Ws, acc, bg, cg);
            float* outp = g_ph + (size_t)s * Bsz * G3H;
#pragma unroll
            for (int i = 0; i < 4; i++) {
                float* o = outp + (size_t)(bg + 8 * i) * G3H + cbase;
#pragma unroll
                for (int j = 0; j < 8; j++) {
                    float2 p = up2(acc[i][j]);
                    o[cg + 16 * j] = p.x + p.y;
                }
            }
        }
        gbar();
        gru_gates(g_gi + (size_t)t * Bsz * G3H, 0, nullptr, 16, g_ph, bhh,
                  h, layer ? nullptr : (g_ys0 + (size_t)t * Bsz * Hsz), NBLK_ENC);
        gbar();
    }
}

// persistent decoder: 64-col tiles, 4 blocks/SM, gh overlapped with FC
__global__ void __launch_bounds__(128, 4) k_dec(
    const float* __restrict__ demb,
    const float* __restrict__ dW0, const float* __restrict__ dU0,
    const float* __restrict__ dbi0, const float* __restrict__ dbh0,
    const float* __restrict__ dW1, const float* __restrict__ dU1,
    const float* __restrict__ dbi1, const float* __restrict__ dbh1,
    const float* __restrict__ fcW, const float* __restrict__ fcb,
    float* __restrict__ out)
{
    extern __shared__ float dyn[];
    float (*AsB)[32][68] = (float(*)[32][68])dyn;                 // 2 x 8704 B
    float (*WsB)[64][68] = (float(*)[64][68])(dyn + 2 * 32 * 68); // 2 x 17408 B
    __shared__ int s_tok[32];
    __shared__ ull sk[32];
    int tid = threadIdx.x, bid = blockIdx.x;
    DecCtx ctx = {demb, dW0, dU0, dW1, dU1, s_tok};

    for (int step = 0; step < Tsz - 1; step++) {
        if (tid < 32)
            s_tok[tid] = (step == 0)
                ? g_tok[tid]
                : (int)(0xFFFFFFFFu - (unsigned)(g_amax[tid] & 0xFFFFFFFFull));
        __syncthreads();
        // P1: gi (384 tasks); at step 0 also ghL0+ghL1 (1920 total)
        run_tasks(0, bid, (step == 0) ? 1920 : 384, NBLK_DEC, ctx, AsB, WsB);
        gbar();
        // P2: gates -> h1 ; reset argmax accumulator
        gru_gates(nullptr, 8, dbi0, 16, g_ph, dbh0, g_h1, nullptr, NBLK_DEC);
        if (bid == 0 && tid < 32) g_amax[tid] = 0ull;
        gbar();
        // P3: gi2 (768 tasks)
        run_tasks(1, bid, 768, NBLK_DEC, ctx, AsB, WsB);
        gbar();
        // P4: gates -> h2 (reads g_ph1)
        gru_gates(nullptr, 16, dbi1, 16, g_ph1, dbh1, g_h2, nullptr, NBLK_DEC);
        gbar();
        // P5: blocks 0-499 FC+argmax; blocks 500-591 next step's ghL0/ghL1
        if (bid < 500)
            run_fc(fcW, fcb, out, step, AsB, WsB, sk);
        else
            run_tasks(0, 384 + (bid - 500), 1920, 92, ctx, AsB, WsB);
        gbar();
    }
}

extern "C" void kernel_launch(void* const* d_in, const int* in_sizes, int n_in,
                              void* d_out, int out_size) {
    const int* src = (const int*)d_in[0];
    const int* trg = (const int*)d_in[1];
    const float* enc_emb = (const float*)d_in[3];
    const float* eW0 = (const float*)d_in[4];
    const float* eU0 = (const float*)d_in[5];
    const float* ebi0 = (const float*)d_in[6];
    const float* ebh0 = (const float*)d_in[7];
    const float* eW1 = (const float*)d_in[8];
    const float* eU1 = (const float*)d_in[9];
    const float* ebi1 = (const float*)d_in[10];
    const float* ebh1 = (const float*)d_in[11];
    const float* demb = (const float*)d_in[12];
    const float* dW0 = (const float*)d_in[13];
    const float* dU0 = (const float*)d_in[14];
    const float* dbi0 = (const float*)d_in[15];
    const float* dbh0 = (const float*)d_in[16];
    const float* dW1 = (const float*)d_in[17];
    const float* dU1 = (const float*)d_in[18];
    const float* dbi1 = (const float*)d_in[19];
    const float* dbh1 = (const float*)d_in[20];
    const float* fcW = (const float*)d_in[21];
    const float* fcb = (const float*)d_in[22];
    float* out = (float*)d_out;

    const int DYN = (2 * 32 * 68 + 2 * 64 * 68) * 4;   // 52224 B
    cudaFuncSetAttribute(k_dec, cudaFuncAttributeMaxDynamicSharedMemorySize, DYN);

    k_init<<<128, 256>>>(trg);
    k_zero0<<<(Bsz * Vsz + 255) / 256, 256>>>(out);

    k_big<<<dim3(24, 128), 128>>>(enc_emb, src, eW0, ebi0, Esz, 1);
    k_enc<<<NBLK_ENC, 128>>>(eU0, ebh0, 0);
    k_big<<<dim3(24, 128), 128>>>(nullptr, nullptr, eW1, ebi1, Hsz, 0);
    k_enc<<<NBLK_ENC, 128>>>(eU1, ebh1, 1);
    k_dec<<<NBLK_DEC, 128, DYN>>>(demb, dW0, dU0, dbi0, dbh0,
                                  dW1, dU1, dbi1, dbh1, fcW, fcb, out);
}